// round 10
// baseline (speedup 1.0000x reference)
#include <cuda_runtime.h>
#include <math.h>
#include <float.h>

#define NB 4
#define NT 1024
#define ND 1024
#define NH 16
#define DH 64
#define RSPAN 256.0f

// ------------------------- scratch (device globals; no allocation) ----------
__device__ float g_Q[NB * NH * NT * DH];
__device__ float g_K[NB * NH * NT * DH];
__device__ float g_V[NB * NH * NT * DH];
__device__ float g_ctx[NB * NT * ND];
__device__ float g_xmean[NB * ND];
__device__ float g_z[NB * NH];

// ------------------------- mean over T ------------------------------------
__global__ __launch_bounds__(256) void mean_kernel(const float* __restrict__ x) {
    int idx = blockIdx.x * 256 + threadIdx.x;      // 0 .. NB*ND-1
    int b = idx >> 10;
    int d = idx & 1023;
    const float* p = x + (size_t)b * NT * ND + d;
    float s = 0.f;
#pragma unroll 8
    for (int t = 0; t < NT; t++) s += p[(size_t)t * ND];
    g_xmean[idx] = s * (1.0f / NT);
}

// ------------------------- span head: z = T*sigmoid(xmean @ Wspan^T + b) ---
__global__ __launch_bounds__(256) void span_kernel(const float* __restrict__ Wspan,
                                                   const float* __restrict__ bspan) {
    int b = blockIdx.x / NH;
    int h = blockIdx.x % NH;
    float s = 0.f;
    for (int d = threadIdx.x; d < ND; d += 256)
        s += g_xmean[b * ND + d] * Wspan[h * ND + d];
    __shared__ float red[256];
    red[threadIdx.x] = s;
    __syncthreads();
    for (int off = 128; off > 0; off >>= 1) {
        if (threadIdx.x < off) red[threadIdx.x] += red[threadIdx.x + off];
        __syncthreads();
    }
    if (threadIdx.x == 0) {
        float logit = red[0] + bspan[h];
        g_z[blockIdx.x] = (float)NT / (1.0f + expf(-logit));
    }
}

// ------------------------- fp32 SGEMM core (C = A @ W^T) -------------------
// 128x128 tile, BK=16, 256 threads, 8x8 register tiles.
#define BM 128
#define BN 128
#define BK 16
#define SPAD 132   // smem row stride (floats), 132 % 32 == 4 -> conflict-free f4 reads

// QKV projection: scatter epilogue into [b][h][t][dh]
__global__ __launch_bounds__(256) void qkv_gemm(const float* __restrict__ x,
                                                const float* __restrict__ Wq,
                                                const float* __restrict__ Wk,
                                                const float* __restrict__ Wv) {
    const float* A = x;
    const float* W = (blockIdx.z == 0) ? Wq : (blockIdx.z == 1 ? Wk : Wv);
    float* out = (blockIdx.z == 0) ? g_Q : (blockIdx.z == 1 ? g_K : g_V);

    __shared__ float As[BK][SPAD];
    __shared__ float Bs[BK][SPAD];

    int m0 = blockIdx.x * BM;
    int n0 = blockIdx.y * BN;
    int tid = threadIdx.x;
    int tx = tid & 15, ty = tid >> 4;

    float acc[8][8] = {};

    int lrow = tid >> 2;            // 0..63
    int lk = (tid & 3) * 4;         // 0,4,8,12

    for (int k0 = 0; k0 < ND; k0 += BK) {
#pragma unroll
        for (int it = 0; it < 2; it++) {
            int r = lrow + it * 64;
            float4 va = *(const float4*)(A + (size_t)(m0 + r) * ND + k0 + lk);
            As[lk + 0][r] = va.x; As[lk + 1][r] = va.y;
            As[lk + 2][r] = va.z; As[lk + 3][r] = va.w;
            float4 vb = *(const float4*)(W + (size_t)(n0 + r) * ND + k0 + lk);
            Bs[lk + 0][r] = vb.x; Bs[lk + 1][r] = vb.y;
            Bs[lk + 2][r] = vb.z; Bs[lk + 3][r] = vb.w;
        }
        __syncthreads();
#pragma unroll
        for (int k = 0; k < BK; k++) {
            float a[8], bb[8];
            *(float4*)&a[0] = *(const float4*)&As[k][ty * 8];
            *(float4*)&a[4] = *(const float4*)&As[k][ty * 8 + 4];
            *(float4*)&bb[0] = *(const float4*)&Bs[k][tx * 8];
            *(float4*)&bb[4] = *(const float4*)&Bs[k][tx * 8 + 4];
#pragma unroll
            for (int i = 0; i < 8; i++)
#pragma unroll
                for (int j = 0; j < 8; j++) acc[i][j] += a[i] * bb[j];
        }
        __syncthreads();
    }

    int n = n0 + tx * 8;
    int h = n >> 6;
    int dd = n & 63;   // tx*8 mod 64 <= 56, so all 8 cols stay in one head
#pragma unroll
    for (int i = 0; i < 8; i++) {
        int m = m0 + ty * 8 + i;
        int b = m >> 10, t = m & 1023;
        float* dst = out + ((((size_t)b * NH + h) * NT + t) * DH + dd);
        *(float4*)dst = make_float4(acc[i][0], acc[i][1], acc[i][2], acc[i][3]);
        *(float4*)(dst + 4) = make_float4(acc[i][4], acc[i][5], acc[i][6], acc[i][7]);
    }
}

// Output projection: out = ctx @ Wo^T + bo
__global__ __launch_bounds__(256) void out_gemm(const float* __restrict__ Wo,
                                                const float* __restrict__ bo,
                                                float* __restrict__ outp) {
    const float* A = g_ctx;
    __shared__ float As[BK][SPAD];
    __shared__ float Bs[BK][SPAD];

    int m0 = blockIdx.x * BM;
    int n0 = blockIdx.y * BN;
    int tid = threadIdx.x;
    int tx = tid & 15, ty = tid >> 4;

    float acc[8][8] = {};
    int lrow = tid >> 2;
    int lk = (tid & 3) * 4;

    for (int k0 = 0; k0 < ND; k0 += BK) {
#pragma unroll
        for (int it = 0; it < 2; it++) {
            int r = lrow + it * 64;
            float4 va = *(const float4*)(A + (size_t)(m0 + r) * ND + k0 + lk);
            As[lk + 0][r] = va.x; As[lk + 1][r] = va.y;
            As[lk + 2][r] = va.z; As[lk + 3][r] = va.w;
            float4 vb = *(const float4*)(Wo + (size_t)(n0 + r) * ND + k0 + lk);
            Bs[lk + 0][r] = vb.x; Bs[lk + 1][r] = vb.y;
            Bs[lk + 2][r] = vb.z; Bs[lk + 3][r] = vb.w;
        }
        __syncthreads();
#pragma unroll
        for (int k = 0; k < BK; k++) {
            float a[8], bb[8];
            *(float4*)&a[0] = *(const float4*)&As[k][ty * 8];
            *(float4*)&a[4] = *(const float4*)&As[k][ty * 8 + 4];
            *(float4*)&bb[0] = *(const float4*)&Bs[k][tx * 8];
            *(float4*)&bb[4] = *(const float4*)&Bs[k][tx * 8 + 4];
#pragma unroll
            for (int i = 0; i < 8; i++)
#pragma unroll
                for (int j = 0; j < 8; j++) acc[i][j] += a[i] * bb[j];
        }
        __syncthreads();
    }

    int n = n0 + tx * 8;
    float4 b0 = *(const float4*)(bo + n);
    float4 b1 = *(const float4*)(bo + n + 4);
#pragma unroll
    for (int i = 0; i < 8; i++) {
        int m = m0 + ty * 8 + i;
        float* dst = outp + (size_t)m * ND + n;
        *(float4*)dst = make_float4(acc[i][0] + b0.x, acc[i][1] + b0.y,
                                    acc[i][2] + b0.z, acc[i][3] + b0.w);
        *(float4*)(dst + 4) = make_float4(acc[i][4] + b1.x, acc[i][5] + b1.y,
                                          acc[i][6] + b1.z, acc[i][7] + b1.w);
    }
}

// ------------------------- attention --------------------------------------
// One block = (qtile of 64, one (b,h)). 128 threads: tx=tid&15 (4 key cols each),
// ty=tid>>4 (8 query rows each). Anti-causal mask (j >= i), online softmax with
// plain sum Z and chi-weighted sum Zc; out = acc / (Zc + 1e-8 * Z).
#define ATTN_SMEM ((64 * 65 * 3 + 64 * 64) * 4)

__global__ __launch_bounds__(128) void attn_kernel() {
    extern __shared__ float sm[];
    float* Qs = sm;                    // [64][65]  (r, k)
    float* Ks = Qs + 64 * 65;          // [64][65]  (c, k)
    float* Ps = Ks + 64 * 65;          // [64][65]  (r, j)
    float* Vs = Ps + 64 * 65;          // [64][64]  (j, d)

    int bh = blockIdx.y;               // b*NH + h
    int qt = blockIdx.x;
    int i0 = qt * 64;
    int tid = threadIdx.x;
    int tx = tid & 15, ty = tid >> 4;

    const float* Qg = g_Q + (size_t)bh * NT * DH;
    const float* Kg = g_K + (size_t)bh * NT * DH;
    const float* Vg = g_V + (size_t)bh * NT * DH;
    float span = RSPAN + g_z[bh];      // chi = clamp((span - d)/R, 0, 1)

    // load Q tile
    for (int idx = tid; idx < 64 * 16; idx += 128) {
        int r = idx >> 4, c4 = (idx & 15) * 4;
        float4 v = *(const float4*)(Qg + (size_t)(i0 + r) * DH + c4);
        Qs[r * 65 + c4 + 0] = v.x; Qs[r * 65 + c4 + 1] = v.y;
        Qs[r * 65 + c4 + 2] = v.z; Qs[r * 65 + c4 + 3] = v.w;
    }

    float m_[8], Zp[8], Zcp[8], acc[8][4];
#pragma unroll
    for (int i = 0; i < 8; i++) {
        m_[i] = -FLT_MAX; Zp[i] = 0.f; Zcp[i] = 0.f;
        acc[i][0] = acc[i][1] = acc[i][2] = acc[i][3] = 0.f;
    }

    for (int jt = qt; jt < NT / 64; jt++) {
        int j0 = jt * 64;
        float dmin = (float)(j0 - (i0 + 63));
        if (dmin >= span) break;       // chi == 0 for whole tile and beyond

        __syncthreads();               // previous Ps/Vs reads done
        for (int idx = tid; idx < 64 * 16; idx += 128) {
            int r = idx >> 4, c4 = (idx & 15) * 4;
            float4 kv = *(const float4*)(Kg + (size_t)(j0 + r) * DH + c4);
            Ks[r * 65 + c4 + 0] = kv.x; Ks[r * 65 + c4 + 1] = kv.y;
            Ks[r * 65 + c4 + 2] = kv.z; Ks[r * 65 + c4 + 3] = kv.w;
            float4 vv = *(const float4*)(Vg + (size_t)(j0 + r) * DH + c4);
            *(float4*)(Vs + r * 64 + c4) = vv;
        }
        __syncthreads();

        // S = Q K^T / 8
        float s[8][4] = {};
#pragma unroll 4
        for (int k = 0; k < 64; k++) {
            float q[8];
#pragma unroll
            for (int i = 0; i < 8; i++) q[i] = Qs[(ty * 8 + i) * 65 + k];
            float kk[4];
#pragma unroll
            for (int j = 0; j < 4; j++) kk[j] = Ks[(tx * 4 + j) * 65 + k];
#pragma unroll
            for (int i = 0; i < 8; i++)
#pragma unroll
                for (int j = 0; j < 4; j++) s[i][j] += q[i] * kk[j];
        }

        bool diag = (jt == qt);
#pragma unroll
        for (int i = 0; i < 8; i++) {
            int gi = i0 + ty * 8 + i;
            float mx = -FLT_MAX;
#pragma unroll
            for (int j = 0; j < 4; j++) {
                int gj = j0 + tx * 4 + j;
                float v = s[i][j] * 0.125f;
                if (diag && gj < gi) v = -FLT_MAX;   // mask: attend to j >= i
                s[i][j] = v;
                mx = fmaxf(mx, v);
            }
            for (int off = 8; off; off >>= 1)
                mx = fmaxf(mx, __shfl_xor_sync(0xffffffffu, mx, off));

            float mnew = fmaxf(m_[i], mx);
            float f = __expf(m_[i] - mnew);
            m_[i] = mnew;
            Zp[i] *= f; Zcp[i] *= f;
#pragma unroll
            for (int j = 0; j < 4; j++) acc[i][j] *= f;

#pragma unroll
            for (int j = 0; j < 4; j++) {
                float e = __expf(s[i][j] - mnew);    // masked -> 0
                int gj = j0 + tx * 4 + j;
                float dd = fmaxf((float)(gj - gi), 0.0f);
                float chi = fminf(fmaxf((span - dd) * (1.0f / RSPAN), 0.0f), 1.0f);
                float p = e * chi;
                Zp[i] += e;
                Zcp[i] += p;
                Ps[(ty * 8 + i) * 65 + tx * 4 + j] = p;
            }
        }
        __syncthreads();

        // acc += P @ V
#pragma unroll 4
        for (int j = 0; j < 64; j++) {
            float4 v4 = *(const float4*)(Vs + j * 64 + tx * 4);
#pragma unroll
            for (int i = 0; i < 8; i++) {
                float p = Ps[(ty * 8 + i) * 65 + j];
                acc[i][0] += p * v4.x; acc[i][1] += p * v4.y;
                acc[i][2] += p * v4.z; acc[i][3] += p * v4.w;
            }
        }
    }

    int b = bh / NH, h = bh % NH;
#pragma unroll
    for (int i = 0; i < 8; i++) {
        float Z = Zp[i], Zc = Zcp[i];
        for (int off = 8; off; off >>= 1) {
            Z += __shfl_xor_sync(0xffffffffu, Z, off);
            Zc += __shfl_xor_sync(0xffffffffu, Zc, off);
        }
        float inv = 1.0f / (Zc + 1e-8f * Z);
        int gi = i0 + ty * 8 + i;
        float* dst = g_ctx + ((size_t)(b * NT + gi)) * ND + h * DH + tx * 4;
        *(float4*)dst = make_float4(acc[i][0] * inv, acc[i][1] * inv,
                                    acc[i][2] * inv, acc[i][3] * inv);
    }
}

// ------------------------- launch -----------------------------------------
extern "C" void kernel_launch(void* const* d_in, const int* in_sizes, int n_in,
                              void* d_out, int out_size) {
    const float* x     = (const float*)d_in[0];
    const float* Wq    = (const float*)d_in[1];
    const float* Wk    = (const float*)d_in[2];
    const float* Wv    = (const float*)d_in[3];
    const float* Wo    = (const float*)d_in[4];
    const float* bo    = (const float*)d_in[5];
    const float* Wspan = (const float*)d_in[6];
    const float* bspan = (const float*)d_in[7];
    float* out = (float*)d_out;

    cudaFuncSetAttribute(attn_kernel, cudaFuncAttributeMaxDynamicSharedMemorySize,
                         ATTN_SMEM);

    mean_kernel<<<(NB * ND) / 256, 256>>>(x);
    span_kernel<<<NB * NH, 256>>>(Wspan, bspan);

    dim3 g1(NB * NT / BM, ND / BN, 3);
    qkv_gemm<<<g1, 256>>>(x, Wq, Wk, Wv);

    dim3 g2(NT / 64, NB * NH);
    attn_kernel<<<g2, 128, ATTN_SMEM>>>();

    dim3 g3(NB * NT / BM, ND / BN);
    out_gemm<<<g3, 256>>>(Wo, bo, out);
}

// round 11
// speedup vs baseline: 1.0020x; 1.0020x over previous
#include <cuda_runtime.h>
#include <math.h>
#include <float.h>

#define NB 4
#define NT 1024
#define ND 1024
#define NH 16
#define DH 64
#define RSPAN 256.0f

// ------------------------- scratch (device globals; no allocation) ----------
__device__ float g_Q[NB * NH * NT * DH];
__device__ float g_K[NB * NH * NT * DH];
__device__ float g_V[NB * NH * NT * DH];
__device__ float g_ctx[NB * NT * ND];
__device__ float g_xmean[NB * ND];
__device__ float g_z[NB * NH];

// ------------------------- mean over T ------------------------------------
__global__ __launch_bounds__(256) void mean_kernel(const float* __restrict__ x) {
    int idx = blockIdx.x * 256 + threadIdx.x;      // 0 .. NB*ND-1
    int b = idx >> 10;
    int d = idx & 1023;
    const float* p = x + (size_t)b * NT * ND + d;
    float s = 0.f;
#pragma unroll 8
    for (int t = 0; t < NT; t++) s += p[(size_t)t * ND];
    g_xmean[idx] = s * (1.0f / NT);
}

// ------------------------- span head: z = T*sigmoid(xmean @ Wspan^T + b) ---
__global__ __launch_bounds__(256) void span_kernel(const float* __restrict__ Wspan,
                                                   const float* __restrict__ bspan) {
    int b = blockIdx.x / NH;
    int h = blockIdx.x % NH;
    float s = 0.f;
    for (int d = threadIdx.x; d < ND; d += 256)
        s += g_xmean[b * ND + d] * Wspan[h * ND + d];
    __shared__ float red[256];
    red[threadIdx.x] = s;
    __syncthreads();
    for (int off = 128; off > 0; off >>= 1) {
        if (threadIdx.x < off) red[threadIdx.x] += red[threadIdx.x + off];
        __syncthreads();
    }
    if (threadIdx.x == 0) {
        float logit = red[0] + bspan[h];
        g_z[blockIdx.x] = (float)NT / (1.0f + expf(-logit));
    }
}

// ------------------------- fp32 SGEMM core (C = A @ W^T) -------------------
// 128x128 tile, BK=16, 256 threads, 8x8 register tiles.
#define BM 128
#define BN 128
#define BK 16
#define SPAD 132   // smem row stride (floats), 132 % 32 == 4 -> conflict-free f4 reads

// QKV projection: scatter epilogue into [b][h][t][dh]
__global__ __launch_bounds__(256) void qkv_gemm(const float* __restrict__ x,
                                                const float* __restrict__ Wq,
                                                const float* __restrict__ Wk,
                                                const float* __restrict__ Wv) {
    const float* A = x;
    const float* W = (blockIdx.z == 0) ? Wq : (blockIdx.z == 1 ? Wk : Wv);
    float* out = (blockIdx.z == 0) ? g_Q : (blockIdx.z == 1 ? g_K : g_V);

    __shared__ float As[BK][SPAD];
    __shared__ float Bs[BK][SPAD];

    int m0 = blockIdx.x * BM;
    int n0 = blockIdx.y * BN;
    int tid = threadIdx.x;
    int tx = tid & 15, ty = tid >> 4;

    float acc[8][8] = {};

    int lrow = tid >> 2;            // 0..63
    int lk = (tid & 3) * 4;         // 0,4,8,12

    for (int k0 = 0; k0 < ND; k0 += BK) {
#pragma unroll
        for (int it = 0; it < 2; it++) {
            int r = lrow + it * 64;
            float4 va = *(const float4*)(A + (size_t)(m0 + r) * ND + k0 + lk);
            As[lk + 0][r] = va.x; As[lk + 1][r] = va.y;
            As[lk + 2][r] = va.z; As[lk + 3][r] = va.w;
            float4 vb = *(const float4*)(W + (size_t)(n0 + r) * ND + k0 + lk);
            Bs[lk + 0][r] = vb.x; Bs[lk + 1][r] = vb.y;
            Bs[lk + 2][r] = vb.z; Bs[lk + 3][r] = vb.w;
        }
        __syncthreads();
#pragma unroll
        for (int k = 0; k < BK; k++) {
            float a[8], bb[8];
            *(float4*)&a[0] = *(const float4*)&As[k][ty * 8];
            *(float4*)&a[4] = *(const float4*)&As[k][ty * 8 + 4];
            *(float4*)&bb[0] = *(const float4*)&Bs[k][tx * 8];
            *(float4*)&bb[4] = *(const float4*)&Bs[k][tx * 8 + 4];
#pragma unroll
            for (int i = 0; i < 8; i++)
#pragma unroll
                for (int j = 0; j < 8; j++) acc[i][j] += a[i] * bb[j];
        }
        __syncthreads();
    }

    int n = n0 + tx * 8;
    int h = n >> 6;
    int dd = n & 63;   // tx*8 mod 64 <= 56, so all 8 cols stay in one head
#pragma unroll
    for (int i = 0; i < 8; i++) {
        int m = m0 + ty * 8 + i;
        int b = m >> 10, t = m & 1023;
        float* dst = out + ((((size_t)b * NH + h) * NT + t) * DH + dd);
        *(float4*)dst = make_float4(acc[i][0], acc[i][1], acc[i][2], acc[i][3]);
        *(float4*)(dst + 4) = make_float4(acc[i][4], acc[i][5], acc[i][6], acc[i][7]);
    }
}

// Output projection: out = ctx @ Wo^T + bo
__global__ __launch_bounds__(256) void out_gemm(const float* __restrict__ Wo,
                                                const float* __restrict__ bo,
                                                float* __restrict__ outp) {
    const float* A = g_ctx;
    __shared__ float As[BK][SPAD];
    __shared__ float Bs[BK][SPAD];

    int m0 = blockIdx.x * BM;
    int n0 = blockIdx.y * BN;
    int tid = threadIdx.x;
    int tx = tid & 15, ty = tid >> 4;

    float acc[8][8] = {};
    int lrow = tid >> 2;
    int lk = (tid & 3) * 4;

    for (int k0 = 0; k0 < ND; k0 += BK) {
#pragma unroll
        for (int it = 0; it < 2; it++) {
            int r = lrow + it * 64;
            float4 va = *(const float4*)(A + (size_t)(m0 + r) * ND + k0 + lk);
            As[lk + 0][r] = va.x; As[lk + 1][r] = va.y;
            As[lk + 2][r] = va.z; As[lk + 3][r] = va.w;
            float4 vb = *(const float4*)(Wo + (size_t)(n0 + r) * ND + k0 + lk);
            Bs[lk + 0][r] = vb.x; Bs[lk + 1][r] = vb.y;
            Bs[lk + 2][r] = vb.z; Bs[lk + 3][r] = vb.w;
        }
        __syncthreads();
#pragma unroll
        for (int k = 0; k < BK; k++) {
            float a[8], bb[8];
            *(float4*)&a[0] = *(const float4*)&As[k][ty * 8];
            *(float4*)&a[4] = *(const float4*)&As[k][ty * 8 + 4];
            *(float4*)&bb[0] = *(const float4*)&Bs[k][tx * 8];
            *(float4*)&bb[4] = *(const float4*)&Bs[k][tx * 8 + 4];
#pragma unroll
            for (int i = 0; i < 8; i++)
#pragma unroll
                for (int j = 0; j < 8; j++) acc[i][j] += a[i] * bb[j];
        }
        __syncthreads();
    }

    int n = n0 + tx * 8;
    float4 b0 = *(const float4*)(bo + n);
    float4 b1 = *(const float4*)(bo + n + 4);
#pragma unroll
    for (int i = 0; i < 8; i++) {
        int m = m0 + ty * 8 + i;
        float* dst = outp + (size_t)m * ND + n;
        *(float4*)dst = make_float4(acc[i][0] + b0.x, acc[i][1] + b0.y,
                                    acc[i][2] + b0.z, acc[i][3] + b0.w);
        *(float4*)(dst + 4) = make_float4(acc[i][4] + b1.x, acc[i][5] + b1.y,
                                          acc[i][6] + b1.z, acc[i][7] + b1.w);
    }
}

// ------------------------- attention --------------------------------------
// One block = (qtile of 64, one (b,h)). 128 threads: tx=tid&15 (4 key cols each),
// ty=tid>>4 (8 query rows each). Anti-causal mask (j >= i), online softmax with
// plain sum Z and chi-weighted sum Zc; out = acc / (Zc + 1e-8 * Z).
#define ATTN_SMEM ((64 * 65 * 3 + 64 * 64) * 4)

__global__ __launch_bounds__(128) void attn_kernel() {
    extern __shared__ float sm[];
    float* Qs = sm;                    // [64][65]  (r, k)
    float* Ks = Qs + 64 * 65;          // [64][65]  (c, k)
    float* Ps = Ks + 64 * 65;          // [64][65]  (r, j)
    float* Vs = Ps + 64 * 65;          // [64][64]  (j, d)

    int bh = blockIdx.y;               // b*NH + h
    int qt = blockIdx.x;
    int i0 = qt * 64;
    int tid = threadIdx.x;
    int tx = tid & 15, ty = tid >> 4;

    const float* Qg = g_Q + (size_t)bh * NT * DH;
    const float* Kg = g_K + (size_t)bh * NT * DH;
    const float* Vg = g_V + (size_t)bh * NT * DH;
    float span = RSPAN + g_z[bh];      // chi = clamp((span - d)/R, 0, 1)

    // load Q tile
    for (int idx = tid; idx < 64 * 16; idx += 128) {
        int r = idx >> 4, c4 = (idx & 15) * 4;
        float4 v = *(const float4*)(Qg + (size_t)(i0 + r) * DH + c4);
        Qs[r * 65 + c4 + 0] = v.x; Qs[r * 65 + c4 + 1] = v.y;
        Qs[r * 65 + c4 + 2] = v.z; Qs[r * 65 + c4 + 3] = v.w;
    }

    float m_[8], Zp[8], Zcp[8], acc[8][4];
#pragma unroll
    for (int i = 0; i < 8; i++) {
        m_[i] = -FLT_MAX; Zp[i] = 0.f; Zcp[i] = 0.f;
        acc[i][0] = acc[i][1] = acc[i][2] = acc[i][3] = 0.f;
    }

    for (int jt = qt; jt < NT / 64; jt++) {
        int j0 = jt * 64;
        float dmin = (float)(j0 - (i0 + 63));
        if (dmin >= span) break;       // chi == 0 for whole tile and beyond

        __syncthreads();               // previous Ps/Vs reads done
        for (int idx = tid; idx < 64 * 16; idx += 128) {
            int r = idx >> 4, c4 = (idx & 15) * 4;
            float4 kv = *(const float4*)(Kg + (size_t)(j0 + r) * DH + c4);
            Ks[r * 65 + c4 + 0] = kv.x; Ks[r * 65 + c4 + 1] = kv.y;
            Ks[r * 65 + c4 + 2] = kv.z; Ks[r * 65 + c4 + 3] = kv.w;
            float4 vv = *(const float4*)(Vg + (size_t)(j0 + r) * DH + c4);
            *(float4*)(Vs + r * 64 + c4) = vv;
        }
        __syncthreads();

        // S = Q K^T / 8
        float s[8][4] = {};
#pragma unroll 4
        for (int k = 0; k < 64; k++) {
            float q[8];
#pragma unroll
            for (int i = 0; i < 8; i++) q[i] = Qs[(ty * 8 + i) * 65 + k];
            float kk[4];
#pragma unroll
            for (int j = 0; j < 4; j++) kk[j] = Ks[(tx * 4 + j) * 65 + k];
#pragma unroll
            for (int i = 0; i < 8; i++)
#pragma unroll
                for (int j = 0; j < 4; j++) s[i][j] += q[i] * kk[j];
        }

        bool diag = (jt == qt);
#pragma unroll
        for (int i = 0; i < 8; i++) {
            int gi = i0 + ty * 8 + i;
            float mx = -FLT_MAX;
#pragma unroll
            for (int j = 0; j < 4; j++) {
                int gj = j0 + tx * 4 + j;
                float v = s[i][j] * 0.125f;
                if (diag && gj < gi) v = -FLT_MAX;   // mask: attend to j >= i
                s[i][j] = v;
                mx = fmaxf(mx, v);
            }
            for (int off = 8; off; off >>= 1)
                mx = fmaxf(mx, __shfl_xor_sync(0xffffffffu, mx, off));

            float mnew = fmaxf(m_[i], mx);
            float f = __expf(m_[i] - mnew);
            m_[i] = mnew;
            Zp[i] *= f; Zcp[i] *= f;
#pragma unroll
            for (int j = 0; j < 4; j++) acc[i][j] *= f;

#pragma unroll
            for (int j = 0; j < 4; j++) {
                float e = __expf(s[i][j] - mnew);    // masked -> 0
                int gj = j0 + tx * 4 + j;
                float dd = fmaxf((float)(gj - gi), 0.0f);
                float chi = fminf(fmaxf((span - dd) * (1.0f / RSPAN), 0.0f), 1.0f);
                float p = e * chi;
                Zp[i] += e;
                Zcp[i] += p;
                Ps[(ty * 8 + i) * 65 + tx * 4 + j] = p;
            }
        }
        __syncthreads();

        // acc += P @ V
#pragma unroll 4
        for (int j = 0; j < 64; j++) {
            float4 v4 = *(const float4*)(Vs + j * 64 + tx * 4);
#pragma unroll
            for (int i = 0; i < 8; i++) {
                float p = Ps[(ty * 8 + i) * 65 + j];
                acc[i][0] += p * v4.x; acc[i][1] += p * v4.y;
                acc[i][2] += p * v4.z; acc[i][3] += p * v4.w;
            }
        }
    }

    int b = bh / NH, h = bh % NH;
#pragma unroll
    for (int i = 0; i < 8; i++) {
        float Z = Zp[i], Zc = Zcp[i];
        for (int off = 8; off; off >>= 1) {
            Z += __shfl_xor_sync(0xffffffffu, Z, off);
            Zc += __shfl_xor_sync(0xffffffffu, Zc, off);
        }
        float inv = 1.0f / (Zc + 1e-8f * Z);
        int gi = i0 + ty * 8 + i;
        float* dst = g_ctx + ((size_t)(b * NT + gi)) * ND + h * DH + tx * 4;
        *(float4*)dst = make_float4(acc[i][0] * inv, acc[i][1] * inv,
                                    acc[i][2] * inv, acc[i][3] * inv);
    }
}

// ------------------------- launch -----------------------------------------
extern "C" void kernel_launch(void* const* d_in, const int* in_sizes, int n_in,
                              void* d_out, int out_size) {
    const float* x     = (const float*)d_in[0];
    const float* Wq    = (const float*)d_in[1];
    const float* Wk    = (const float*)d_in[2];
    const float* Wv    = (const float*)d_in[3];
    const float* Wo    = (const float*)d_in[4];
    const float* bo    = (const float*)d_in[5];
    const float* Wspan = (const float*)d_in[6];
    const float* bspan = (const float*)d_in[7];
    float* out = (float*)d_out;

    cudaFuncSetAttribute(attn_kernel, cudaFuncAttributeMaxDynamicSharedMemorySize,
                         ATTN_SMEM);

    mean_kernel<<<(NB * ND) / 256, 256>>>(x);
    span_kernel<<<NB * NH, 256>>>(Wspan, bspan);

    dim3 g1(NB * NT / BM, ND / BN, 3);
    qkv_gemm<<<g1, 256>>>(x, Wq, Wk, Wv);

    dim3 g2(NT / 64, NB * NH);
    attn_kernel<<<g2, 128, ATTN_SMEM>>>();

    dim3 g3(NB * NT / BM, ND / BN);
    out_gemm<<<g3, 256>>>(Wo, bo, out);
}